// round 9
// baseline (speedup 1.0000x reference)
#include <cuda_runtime.h>
#include <cuda_fp16.h>
#include <cstdint>

// ---------------------------------------------------------------------------
// out[n,o] = sum_s attn[s] * (X[s] @ W[s])[n,o] + bias[o]
// R9: warp-specialized. 8 MMA warps + 4 producer warps (fp32->fp16 convert).
//     A: 32KB half-support bulks, 2-slot ring. Staging fp16: 2x32KB ring.
//     B: 2x32KB ring (pre-swizzled stage-major). All handoffs by mbarrier;
//     no __syncthreads in the main loop.
// ---------------------------------------------------------------------------

#define NROWS    200000
#define BLOCK_M  128
#define NSUP     8

#define AH_BYTES  32768        // 64 rows x 512B fp32 (half support)
#define STG_BYTES 32768        // 128 rows x 128 cols fp16 (swizzled)
#define B_BYTES   32768

// mbarrier offsets (each 2 slots x 8B)
#define MB_AHF 0               // A half full (tx)
#define MB_SF  16              // staging full  (count 1, arrived by tid 256)
#define MB_SE  32              // staging free  (count 8, consumer warps)
#define MB_BF  48              // B full (tx)
#define MB_BE  64              // B free (count 8)

#define SMEM_A0   1024
#define SMEM_STG  (SMEM_A0 + 2 * AH_BYTES)      // 66560
#define SMEM_B0   (SMEM_STG + 2 * STG_BYTES)    // 132096
#define SMEM_TOTAL (SMEM_B0 + 2 * B_BYTES)      // 197632

// B: stage-major fp16, attn-folded, swizzled: (s,o,i) ->
//   s*16384 + o*128 + ((i>>3) ^ (o&7))*8 + (i&7)
__device__ __half g_Wh[NSUP * 128 * 128];

// ---- helpers ---------------------------------------------------------------

__device__ __forceinline__ uint32_t smem_u32(const void* p) {
    uint32_t a;
    asm("{ .reg .u64 t; cvta.to.shared.u64 t, %1; cvt.u32.u64 %0, t; }"
        : "=r"(a) : "l"(p));
    return a;
}

__device__ __forceinline__ void ldsm_x4(uint32_t* r, uint32_t addr) {
    asm volatile("ldmatrix.sync.aligned.m8n8.x4.shared.b16 {%0,%1,%2,%3}, [%4];"
                 : "=r"(r[0]), "=r"(r[1]), "=r"(r[2]), "=r"(r[3]) : "r"(addr));
}

__device__ __forceinline__ void mma_f16(float* c, const uint32_t* a,
                                        uint32_t b0, uint32_t b1) {
    asm volatile(
        "mma.sync.aligned.m16n8k16.row.col.f32.f16.f16.f32 "
        "{%0,%1,%2,%3}, {%4,%5,%6,%7}, {%8,%9}, {%0,%1,%2,%3};"
        : "+f"(c[0]), "+f"(c[1]), "+f"(c[2]), "+f"(c[3])
        : "r"(a[0]), "r"(a[1]), "r"(a[2]), "r"(a[3]), "r"(b0), "r"(b1));
}

__device__ __forceinline__ void mbar_wait(uint32_t mbar, uint32_t parity) {
    asm volatile(
        "{\n\t"
        ".reg .pred P1;\n\t"
        "WAIT_LOOP_%=:\n\t"
        "mbarrier.try_wait.parity.acquire.cta.shared::cta.b64 P1, [%0], %1, 0x989680;\n\t"
        "@P1 bra.uni WAIT_DONE_%=;\n\t"
        "bra.uni WAIT_LOOP_%=;\n\t"
        "WAIT_DONE_%=:\n\t"
        "}"
        :: "r"(mbar), "r"(parity) : "memory");
}

__device__ __forceinline__ void mbar_arrive(uint32_t mbar) {
    asm volatile("mbarrier.arrive.release.cta.shared::cta.b64 _, [%0];"
                 :: "r"(mbar) : "memory");
}

// A half-stage h: support h>>1, half h&1, into slot h&1.
__device__ __forceinline__ void issue_A(const float* __restrict__ X,
                                        uint32_t sb, int h, int m0) {
    const int slot = h & 1;
    const int s    = h >> 1;
    const int row0 = m0 + (slot << 6);
    int avail = NROWS - row0;
    uint32_t bytes;
    const float* src;
    if (avail >= 64)      { bytes = 64 * 512;  src = X + ((size_t)s * NROWS + row0) * 128; }
    else if (avail > 0)   { bytes = (uint32_t)avail * 512; src = X + ((size_t)s * NROWS + row0) * 128; }
    else                  { bytes = 512; src = X; }   // dummy; rows masked at store
    const uint32_t mbar = sb + MB_AHF + slot * 8;
    asm volatile("mbarrier.arrive.expect_tx.shared.b64 _, [%0], %1;"
                 :: "r"(mbar), "r"(bytes) : "memory");
    asm volatile(
        "cp.async.bulk.shared::cta.global.mbarrier::complete_tx::bytes "
        "[%0], [%1], %2, [%3];"
        :: "r"(sb + SMEM_A0 + slot * AH_BYTES), "l"(src), "r"(bytes), "r"(mbar)
        : "memory");
}

__device__ __forceinline__ void issue_B(uint32_t sb, int slot, int s) {
    const uint32_t mbar = sb + MB_BF + slot * 8;
    asm volatile("mbarrier.arrive.expect_tx.shared.b64 _, [%0], %1;"
                 :: "r"(mbar), "r"((uint32_t)B_BYTES) : "memory");
    const void* gB = (const void*)(g_Wh + (size_t)s * 16384);
    asm volatile(
        "cp.async.bulk.shared::cta.global.mbarrier::complete_tx::bytes "
        "[%0], [%1], %2, [%3];"
        :: "r"(sb + SMEM_B0 + slot * B_BYTES), "l"(gB), "r"((uint32_t)B_BYTES),
           "r"(mbar) : "memory");
}

// ---- prep: stage-major, ldmatrix-swizzled fp16 B ----------------------------

__global__ void prep_kernel(const float* __restrict__ W, const float* __restrict__ attn) {
    int idx = blockIdx.x * 256 + threadIdx.x;
    if (idx >= NSUP * 128 * 128) return;
    int s = idx >> 14;
    int o = (idx >> 7) & 127;
    int i = idx & 127;
    float v = attn[s] * W[((s << 7) + i) * 128 + o];
    int dst = s * 16384 + o * 128 + ((((i >> 3) ^ (o & 7))) << 3) + (i & 7);
    g_Wh[dst] = __float2half_rn(v);
}

// ---- main GEMM --------------------------------------------------------------

__global__ void __launch_bounds__(384, 1)
mgc_kernel(const float* __restrict__ X, const float* __restrict__ bias,
           float* __restrict__ out) {
    extern __shared__ char smem[];
    const uint32_t sb  = smem_u32(smem);
    const int tid = threadIdx.x;
    const int lid = tid & 31;
    const int m0  = blockIdx.x * BLOCK_M;

    if (tid == 0) {
        // counts: AHF 1(tx), SF 1, SE 8, BF 1(tx), BE 8
        asm volatile("mbarrier.init.shared.b64 [%0], 1;" :: "r"(sb + MB_AHF)      : "memory");
        asm volatile("mbarrier.init.shared.b64 [%0], 1;" :: "r"(sb + MB_AHF + 8)  : "memory");
        asm volatile("mbarrier.init.shared.b64 [%0], 1;" :: "r"(sb + MB_SF)       : "memory");
        asm volatile("mbarrier.init.shared.b64 [%0], 1;" :: "r"(sb + MB_SF + 8)   : "memory");
        asm volatile("mbarrier.init.shared.b64 [%0], 8;" :: "r"(sb + MB_SE)       : "memory");
        asm volatile("mbarrier.init.shared.b64 [%0], 8;" :: "r"(sb + MB_SE + 8)   : "memory");
        asm volatile("mbarrier.init.shared.b64 [%0], 1;" :: "r"(sb + MB_BF)       : "memory");
        asm volatile("mbarrier.init.shared.b64 [%0], 1;" :: "r"(sb + MB_BF + 8)   : "memory");
        asm volatile("mbarrier.init.shared.b64 [%0], 8;" :: "r"(sb + MB_BE)       : "memory");
        asm volatile("mbarrier.init.shared.b64 [%0], 8;" :: "r"(sb + MB_BE + 8)   : "memory");
        asm volatile("fence.proxy.async.shared::cta;" ::: "memory");
    }
    __syncthreads();
    if (tid == 256) {
        issue_A(X, sb, 0, m0);
        issue_A(X, sb, 1, m0);
        issue_B(sb, 0, 0);
        issue_B(sb, 1, 1);
    }

    if (tid >= 256) {
        // =================== PRODUCERS (4 warps) ============================
        const int q = tid - 256;                 // 0..127
        for (int h = 0; h < 2 * NSUP; h++) {
            const int slot  = h & 1;             // A slot == half
            const int s     = h >> 1;
            const int sslot = s & 1;
            mbar_wait(sb + MB_AHF + slot * 8, (h >> 1) & 1);
            if (slot == 0 && s >= 2)
                mbar_wait(sb + MB_SE + sslot * 8, ((s - 2) >> 1) & 1);

            const uint32_t aSlot = sb + SMEM_A0 + slot * AH_BYTES;
            const uint32_t stg   = sb + SMEM_STG + sslot * STG_BYTES;
            #pragma unroll
            for (int i = 0; i < 16; i++) {
                int f  = q + (i << 7);           // 0..2047
                int c  = f >> 9;
                int rw = (f >> 3) & 63;
                int fc = f & 7;
                float x, y, z, w;
                asm("ld.shared.v4.f32 {%0,%1,%2,%3}, [%4];"
                    : "=f"(x), "=f"(y), "=f"(z), "=f"(w)
                    : "r"(aSlot + (uint32_t)(rw * 512 + c * 128 + fc * 16)));
                uint32_t h0, h1;
                asm("cvt.rn.f16x2.f32 %0, %1, %2;" : "=r"(h0) : "f"(y), "f"(x));
                asm("cvt.rn.f16x2.f32 %0, %1, %2;" : "=r"(h1) : "f"(w), "f"(z));
                int grow = rw + (slot << 6);
                int phys = (fc >> 1) ^ ((rw >> 1) & 3);
                asm volatile("st.shared.v2.b32 [%0], {%1,%2};"
                    :: "r"(stg + (uint32_t)(c * 8192 + grow * 64 + phys * 16 + (fc & 1) * 8)),
                       "r"(h0), "r"(h1) : "memory");
            }
            asm volatile("bar.sync 1, 128;" ::: "memory");   // producers only
            if (tid == 256) {
                if (h + 2 < 2 * NSUP) issue_A(X, sb, h + 2, m0);
                if (slot == 1) mbar_arrive(sb + MB_SF + sslot * 8);
            }
        }
    } else {
        // =================== CONSUMERS (8 MMA warps) ========================
        const int wid = tid >> 5;
        const int wm  = wid >> 1;
        const int wn  = wid & 1;

        const int rA_base = wm * 32 + (lid & 15);
        const int a_usel  = (lid >> 4) & 1;
        const int o_base  = wn * 64 + (lid & 7) + ((lid >> 4) & 1) * 8;
        const int b_usel  = (lid >> 3) & 1;

        float acc[2][8][4];
        #pragma unroll
        for (int mt = 0; mt < 2; mt++)
            #pragma unroll
            for (int nt = 0; nt < 8; nt++)
                #pragma unroll
                for (int v = 0; v < 4; v++) acc[mt][nt][v] = 0.f;

        for (int s = 0; s < NSUP; s++) {
            const int sslot = s & 1;
            const uint32_t par = (s >> 1) & 1;
            mbar_wait(sb + MB_SF + sslot * 8, par);
            mbar_wait(sb + MB_BF + sslot * 8, par);

            const uint32_t stg   = sb + SMEM_STG + sslot * STG_BYTES;
            const uint32_t bSlot = sb + SMEM_B0 + sslot * B_BYTES;

            #pragma unroll
            for (int c = 0; c < 4; c++) {
                #pragma unroll
                for (int jl = 0; jl < 2; jl++) {
                    uint32_t af[2][4];
                    #pragma unroll
                    for (int mt = 0; mt < 2; mt++) {
                        int r = rA_base + mt * 16;
                        int u = 2 * jl + a_usel;
                        uint32_t addr = stg + (uint32_t)(c * 8192 + r * 64 +
                                           ((u ^ ((r >> 1) & 3)) << 4));
                        ldsm_x4(af[mt], addr);
                    }
                    uint32_t bq[4][4];
                    #pragma unroll
                    for (int p = 0; p < 4; p++) {
                        int o = o_base + 16 * p;
                        int u = 4 * c + 2 * jl + b_usel;
                        uint32_t addr = bSlot + (uint32_t)(o * 256 +
                                            ((u ^ (o & 7)) << 4));
                        ldsm_x4(bq[p], addr);
                    }
                    #pragma unroll
                    for (int mt = 0; mt < 2; mt++)
                        #pragma unroll
                        for (int p = 0; p < 4; p++) {
                            mma_f16(acc[mt][2 * p],     af[mt], bq[p][0], bq[p][1]);
                            mma_f16(acc[mt][2 * p + 1], af[mt], bq[p][2], bq[p][3]);
                        }
                }
            }

            __syncwarp();
            if (lid == 0) {
                mbar_arrive(sb + MB_SE + sslot * 8);
                mbar_arrive(sb + MB_BE + sslot * 8);
            }
            // consumer warp 0 refills the B ring (producers never block on MMA)
            if (wid == 0 && lid == 0 && s + 2 < NSUP) {
                mbar_wait(sb + MB_BE + sslot * 8, (s >> 1) & 1);
                issue_B(sb, sslot, s + 2);
            }
        }

        // ---- epilogue: acc + bias -> out ------------------------------------
        const int tig = lid & 3;
        const int g   = lid >> 2;

        float2 bv[8];
        #pragma unroll
        for (int nt = 0; nt < 8; nt++) {
            int cidx = wn * 64 + nt * 8 + 2 * tig;
            bv[nt].x = __ldg(&bias[cidx]);
            bv[nt].y = __ldg(&bias[cidx + 1]);
        }

        #pragma unroll
        for (int mt = 0; mt < 2; mt++) {
            int mrow = m0 + wm * 32 + mt * 16 + g;
            #pragma unroll
            for (int half = 0; half < 2; half++) {
                int m = mrow + half * 8;
                if (m < NROWS) {
                    float* po = out + (size_t)m * 128 + wn * 64;
                    #pragma unroll
                    for (int nt = 0; nt < 8; nt++) {
                        float2 v;
                        v.x = acc[mt][nt][2 * half + 0] + bv[nt].x;
                        v.y = acc[mt][nt][2 * half + 1] + bv[nt].y;
                        *reinterpret_cast<float2*>(po + nt * 8 + 2 * tig) = v;
                    }
                }
            }
        }
    }
}

// ---- launch -----------------------------------------------------------------

extern "C" void kernel_launch(void* const* d_in, const int* in_sizes, int n_in,
                              void* d_out, int out_size) {
    const float* X    = (const float*)d_in[0];   // (8, 200000, 128) f32
    const float* W    = (const float*)d_in[1];   // (8, 128, 128)    f32
    const float* attn = (const float*)d_in[2];   // (8,)             f32
    const float* bias = (const float*)d_in[3];   // (128,)           f32
    float* out = (float*)d_out;                  // (200000, 128)    f32

    cudaFuncSetAttribute(mgc_kernel, cudaFuncAttributeMaxDynamicSharedMemorySize,
                         SMEM_TOTAL);

    prep_kernel<<<(NSUP * 128 * 128 + 255) / 256, 256>>>(W, attn);

    int grid = (NROWS + BLOCK_M - 1) / BLOCK_M;   // 1563
    mgc_kernel<<<grid, 384, SMEM_TOTAL>>>(X, bias, out);
}

// round 10
// speedup vs baseline: 1.1538x; 1.1538x over previous
#include <cuda_runtime.h>
#include <cuda_fp16.h>
#include <cstdint>

// ---------------------------------------------------------------------------
// out[n,o] = sum_s attn[s] * (X[s] @ W[s])[n,o] + bias[o]
// R10: 4 MMA warps (64x64 tiles) + 4 producer warps (fp32->fp16 convert).
//      A: half-support 32KB bulks, ring 3. Staging fp16 ring 2. B ring 2.
// ---------------------------------------------------------------------------

#define NROWS    200000
#define BLOCK_M  128
#define NSUP     8

#define AH_BYTES  32768        // 64 rows x 512B fp32 (half support)
#define STG_BYTES 32768        // 128 x 128 fp16 (swizzled)
#define B_BYTES   32768

// mbarriers
#define MB_AHF 0               // 3 slots (tx)
#define MB_SF  24              // 2 slots (count 1)
#define MB_SE  40              // 2 slots (count 1)
#define MB_BF  56              // 2 slots (tx)

#define SMEM_A0   1024
#define SMEM_STG  (SMEM_A0 + 3 * AH_BYTES)       // 99328 + 1024 = 100352
#define SMEM_B0   (SMEM_STG + 2 * STG_BYTES)     // 165888
#define SMEM_TOTAL (SMEM_B0 + 2 * B_BYTES)       // 231424 (<= 232448)

// B: stage-major fp16, attn-folded, swizzled: (s,o,i) ->
//   s*16384 + o*128 + ((i>>3) ^ (o&7))*8 + (i&7)
__device__ __half g_Wh[NSUP * 128 * 128];

// ---- helpers ---------------------------------------------------------------

__device__ __forceinline__ uint32_t smem_u32(const void* p) {
    uint32_t a;
    asm("{ .reg .u64 t; cvta.to.shared.u64 t, %1; cvt.u32.u64 %0, t; }"
        : "=r"(a) : "l"(p));
    return a;
}

__device__ __forceinline__ void ldsm_x4(uint32_t* r, uint32_t addr) {
    asm volatile("ldmatrix.sync.aligned.m8n8.x4.shared.b16 {%0,%1,%2,%3}, [%4];"
                 : "=r"(r[0]), "=r"(r[1]), "=r"(r[2]), "=r"(r[3]) : "r"(addr));
}

__device__ __forceinline__ void mma_f16(float* c, const uint32_t* a,
                                        uint32_t b0, uint32_t b1) {
    asm volatile(
        "mma.sync.aligned.m16n8k16.row.col.f32.f16.f16.f32 "
        "{%0,%1,%2,%3}, {%4,%5,%6,%7}, {%8,%9}, {%0,%1,%2,%3};"
        : "+f"(c[0]), "+f"(c[1]), "+f"(c[2]), "+f"(c[3])
        : "r"(a[0]), "r"(a[1]), "r"(a[2]), "r"(a[3]), "r"(b0), "r"(b1));
}

__device__ __forceinline__ void mbar_wait(uint32_t mbar, uint32_t parity) {
    asm volatile(
        "{\n\t"
        ".reg .pred P1;\n\t"
        "WAIT_LOOP_%=:\n\t"
        "mbarrier.try_wait.parity.acquire.cta.shared::cta.b64 P1, [%0], %1, 0x989680;\n\t"
        "@P1 bra.uni WAIT_DONE_%=;\n\t"
        "bra.uni WAIT_LOOP_%=;\n\t"
        "WAIT_DONE_%=:\n\t"
        "}"
        :: "r"(mbar), "r"(parity) : "memory");
}

__device__ __forceinline__ void mbar_arrive(uint32_t mbar) {
    asm volatile("mbarrier.arrive.release.cta.shared::cta.b64 _, [%0];"
                 :: "r"(mbar) : "memory");
}

// issue A half h (support h>>1, half h&1) into slot h%3
__device__ __forceinline__ void issue_A(const float* __restrict__ X,
                                        uint32_t sb, int h, int m0) {
    const int slot = h % 3;
    const int s    = h >> 1;
    const int row0 = m0 + (h & 1) * 64;
    int avail = NROWS - row0;
    uint32_t bytes;
    const float* src;
    if (avail >= 64)    { bytes = 64 * 512; src = X + ((size_t)s * NROWS + row0) * 128; }
    else if (avail > 0) { bytes = (uint32_t)avail * 512; src = X + ((size_t)s * NROWS + row0) * 128; }
    else                { bytes = 512; src = X; }
    const uint32_t mbar = sb + MB_AHF + slot * 8;
    asm volatile("mbarrier.arrive.expect_tx.shared.b64 _, [%0], %1;"
                 :: "r"(mbar), "r"(bytes) : "memory");
    asm volatile(
        "cp.async.bulk.shared::cta.global.mbarrier::complete_tx::bytes "
        "[%0], [%1], %2, [%3];"
        :: "r"(sb + SMEM_A0 + slot * AH_BYTES), "l"(src), "r"(bytes), "r"(mbar)
        : "memory");
}

__device__ __forceinline__ void issue_B(uint32_t sb, int slot, int s) {
    const uint32_t mbar = sb + MB_BF + slot * 8;
    asm volatile("mbarrier.arrive.expect_tx.shared.b64 _, [%0], %1;"
                 :: "r"(mbar), "r"((uint32_t)B_BYTES) : "memory");
    const void* gB = (const void*)(g_Wh + (size_t)s * 16384);
    asm volatile(
        "cp.async.bulk.shared::cta.global.mbarrier::complete_tx::bytes "
        "[%0], [%1], %2, [%3];"
        :: "r"(sb + SMEM_B0 + slot * B_BYTES), "l"(gB), "r"((uint32_t)B_BYTES),
           "r"(mbar) : "memory");
}

// ---- prep: stage-major, ldmatrix-swizzled fp16 B ----------------------------

__global__ void prep_kernel(const float* __restrict__ W, const float* __restrict__ attn) {
    int idx = blockIdx.x * 256 + threadIdx.x;
    if (idx >= NSUP * 128 * 128) return;
    int s = idx >> 14;
    int o = (idx >> 7) & 127;
    int i = idx & 127;
    float v = attn[s] * W[((s << 7) + i) * 128 + o];
    int dst = s * 16384 + o * 128 + ((((i >> 3) ^ (o & 7))) << 3) + (i & 7);
    g_Wh[dst] = __float2half_rn(v);
}

// ---- main GEMM --------------------------------------------------------------

__global__ void __launch_bounds__(256, 1)
mgc_kernel(const float* __restrict__ X, const float* __restrict__ bias,
           float* __restrict__ out) {
    extern __shared__ char smem[];
    const uint32_t sb  = smem_u32(smem);
    const int tid = threadIdx.x;
    const int lid = tid & 31;
    const int m0  = blockIdx.x * BLOCK_M;

    if (tid == 0) {
        #pragma unroll
        for (int j = 0; j < 3; j++)
            asm volatile("mbarrier.init.shared.b64 [%0], 1;"
                         :: "r"(sb + MB_AHF + j * 8) : "memory");
        asm volatile("mbarrier.init.shared.b64 [%0], 1;" :: "r"(sb + MB_SF)     : "memory");
        asm volatile("mbarrier.init.shared.b64 [%0], 1;" :: "r"(sb + MB_SF + 8) : "memory");
        asm volatile("mbarrier.init.shared.b64 [%0], 1;" :: "r"(sb + MB_SE)     : "memory");
        asm volatile("mbarrier.init.shared.b64 [%0], 1;" :: "r"(sb + MB_SE + 8) : "memory");
        asm volatile("mbarrier.init.shared.b64 [%0], 1;" :: "r"(sb + MB_BF)     : "memory");
        asm volatile("mbarrier.init.shared.b64 [%0], 1;" :: "r"(sb + MB_BF + 8) : "memory");
        asm volatile("fence.proxy.async.shared::cta;" ::: "memory");
    }
    __syncthreads();
    if (tid == 128) {
        issue_A(X, sb, 0, m0);
        issue_A(X, sb, 1, m0);
        issue_A(X, sb, 2, m0);
        issue_B(sb, 0, 0);
        issue_B(sb, 1, 1);
    }

    if (tid >= 128) {
        // =================== PRODUCERS (warps 4-7) ==========================
        const int q = tid - 128;                 // 0..127
        for (int h = 0; h < 2 * NSUP; h++) {
            const int s = h >> 1;
            const int p = s & 1;                 // staging slot
            if ((h & 1) == 0 && s >= 2)          // first write of stg[p] for s
                mbar_wait(sb + MB_SE + p * 8, ((s - 2) >> 1) & 1);
            mbar_wait(sb + MB_AHF + (h % 3) * 8, (uint32_t)((h / 3) & 1));

            const uint32_t aSlot = sb + SMEM_A0 + (h % 3) * AH_BYTES;
            const uint32_t stg   = sb + SMEM_STG + p * STG_BYTES;
            const int rowoff = (h & 1) * 64;
            #pragma unroll
            for (int i = 0; i < 16; i++) {
                int f  = q + (i << 7);           // 0..2047
                int c  = f >> 9;
                int rw = (f >> 3) & 63;
                int fc = f & 7;
                float x, y, z, w;
                asm("ld.shared.v4.f32 {%0,%1,%2,%3}, [%4];"
                    : "=f"(x), "=f"(y), "=f"(z), "=f"(w)
                    : "r"(aSlot + (uint32_t)(rw * 512 + c * 128 + fc * 16)));
                uint32_t h0, h1;
                asm("cvt.rn.f16x2.f32 %0, %1, %2;" : "=r"(h0) : "f"(y), "f"(x));
                asm("cvt.rn.f16x2.f32 %0, %1, %2;" : "=r"(h1) : "f"(w), "f"(z));
                int grow = rw + rowoff;
                int phys = (fc >> 1) ^ ((rw >> 1) & 3);
                asm volatile("st.shared.v2.b32 [%0], {%1,%2};"
                    :: "r"(stg + (uint32_t)(c * 8192 + grow * 64 + phys * 16 + (fc & 1) * 8)),
                       "r"(h0), "r"(h1) : "memory");
            }
            asm volatile("bar.sync 1, 128;" ::: "memory");   // producers only
            if (tid == 128) {
                if (h + 3 < 2 * NSUP) issue_A(X, sb, h + 3, m0);
                if (h & 1) mbar_arrive(sb + MB_SF + p * 8);
            }
        }
    } else {
        // =================== CONSUMERS (warps 0-3, 64x64 tiles) ============
        const int wid = tid >> 5;
        const int wm  = wid >> 1;                // 0..1
        const int wn  = wid & 1;                 // 0..1

        const int rA_base = wm * 64 + (lid & 15);            // + mt*16
        const int a_usel  = (lid >> 4) & 1;
        const int o_base  = wn * 64 + (lid & 7) + ((lid >> 4) & 1) * 8;  // + 16*p
        const int b_usel  = (lid >> 3) & 1;

        float acc[4][8][4];
        #pragma unroll
        for (int mt = 0; mt < 4; mt++)
            #pragma unroll
            for (int nt = 0; nt < 8; nt++)
                #pragma unroll
                for (int v = 0; v < 4; v++) acc[mt][nt][v] = 0.f;

        for (int s = 0; s < NSUP; s++) {
            const int p = s & 1;
            const uint32_t par = (s >> 1) & 1;
            mbar_wait(sb + MB_SF + p * 8, par);
            mbar_wait(sb + MB_BF + p * 8, par);

            const uint32_t stg   = sb + SMEM_STG + p * STG_BYTES;
            const uint32_t bSlot = sb + SMEM_B0 + p * B_BYTES;

            #pragma unroll
            for (int c = 0; c < 4; c++) {
                #pragma unroll
                for (int jl = 0; jl < 2; jl++) {
                    uint32_t af[4][4];
                    #pragma unroll
                    for (int mt = 0; mt < 4; mt++) {
                        int r = rA_base + mt * 16;
                        int u = 2 * jl + a_usel;
                        uint32_t addr = stg + (uint32_t)(c * 8192 + r * 64 +
                                           ((u ^ ((r >> 1) & 3)) << 4));
                        ldsm_x4(af[mt], addr);
                    }
                    uint32_t bq[4][4];
                    #pragma unroll
                    for (int pp = 0; pp < 4; pp++) {
                        int o = o_base + 16 * pp;
                        int u = 4 * c + 2 * jl + b_usel;
                        uint32_t addr = bSlot + (uint32_t)(o * 256 +
                                            ((u ^ (o & 7)) << 4));
                        ldsm_x4(bq[pp], addr);
                    }
                    #pragma unroll
                    for (int mt = 0; mt < 4; mt++)
                        #pragma unroll
                        for (int pp = 0; pp < 4; pp++) {
                            mma_f16(acc[mt][2 * pp],     af[mt], bq[pp][0], bq[pp][1]);
                            mma_f16(acc[mt][2 * pp + 1], af[mt], bq[pp][2], bq[pp][3]);
                        }
                }
            }

            asm volatile("bar.sync 2, 128;" ::: "memory");   // 4 MMA warps done
            if (tid == 0) {
                mbar_arrive(sb + MB_SE + p * 8);             // staging p free
                if (s + 2 < NSUP) issue_B(sb, p, s + 2);     // B slot p free
            }
        }

        // ---- epilogue: acc + bias -> out ------------------------------------
        const int tig = lid & 3;
        const int g   = lid >> 2;

        float2 bv[8];
        #pragma unroll
        for (int nt = 0; nt < 8; nt++) {
            int cidx = wn * 64 + nt * 8 + 2 * tig;
            bv[nt].x = __ldg(&bias[cidx]);
            bv[nt].y = __ldg(&bias[cidx + 1]);
        }

        #pragma unroll
        for (int mt = 0; mt < 4; mt++) {
            int mrow = m0 + wm * 64 + mt * 16 + g;
            #pragma unroll
            for (int half = 0; half < 2; half++) {
                int m = mrow + half * 8;
                if (m < NROWS) {
                    float* po = out + (size_t)m * 128 + wn * 64;
                    #pragma unroll
                    for (int nt = 0; nt < 8; nt++) {
                        float2 v;
                        v.x = acc[mt][nt][2 * half + 0] + bv[nt].x;
                        v.y = acc[mt][nt][2 * half + 1] + bv[nt].y;
                        *reinterpret_cast<float2*>(po + nt * 8 + 2 * tig) = v;
                    }
                }
            }
        }
    }
}

// ---- launch -----------------------------------------------------------------

extern "C" void kernel_launch(void* const* d_in, const int* in_sizes, int n_in,
                              void* d_out, int out_size) {
    const float* X    = (const float*)d_in[0];   // (8, 200000, 128) f32
    const float* W    = (const float*)d_in[1];   // (8, 128, 128)    f32
    const float* attn = (const float*)d_in[2];   // (8,)             f32
    const float* bias = (const float*)d_in[3];   // (128,)           f32
    float* out = (float*)d_out;                  // (200000, 128)    f32

    cudaFuncSetAttribute(mgc_kernel, cudaFuncAttributeMaxDynamicSharedMemorySize,
                         SMEM_TOTAL);

    prep_kernel<<<(NSUP * 128 * 128 + 255) / 256, 256>>>(W, attn);

    int grid = (NROWS + BLOCK_M - 1) / BLOCK_M;   // 1563
    mgc_kernel<<<grid, 256, SMEM_TOTAL>>>(X, bias, out);
}

// round 11
// speedup vs baseline: 1.3307x; 1.1534x over previous
#include <cuda_runtime.h>
#include <cuda_fp16.h>
#include <cstdint>

// ---------------------------------------------------------------------------
// out[n,o] = sum_s attn[s] * (X[s] @ W[s])[n,o] + bias[o]
// R11: persistent CTAs (grid=148). 4 MMA warps (64x64) + 4 producer warps.
//      Rings/phases continue across M-tiles: DMA overlaps epilogues, no tail.
// ---------------------------------------------------------------------------

#define NROWS    200000
#define BLOCK_M  128
#define NSUP     8
#define NTILES   1563               // ceil(200000/128)
#define GRID     148

#define AH_BYTES  32768             // 64 rows x 512B fp32 (half support)
#define STG_BYTES 32768             // 128 x 128 fp16 (swizzled)
#define B_BYTES   32768

// mbarriers
#define MB_AHF 0                    // 3 slots (tx)
#define MB_SF  24                   // 2 slots
#define MB_SE  40                   // 2 slots
#define MB_BF  56                   // 2 slots (tx)

#define SMEM_A0   1024
#define SMEM_STG  (SMEM_A0 + 3 * AH_BYTES)
#define SMEM_B0   (SMEM_STG + 2 * STG_BYTES)
#define SMEM_TOTAL (SMEM_B0 + 2 * B_BYTES)       // 231424

// B: stage-major fp16, attn-folded, swizzled: (s,o,i) ->
//   s*16384 + o*128 + ((i>>3) ^ (o&7))*8 + (i&7)
__device__ __half g_Wh[NSUP * 128 * 128];

// ---- helpers ---------------------------------------------------------------

__device__ __forceinline__ uint32_t smem_u32(const void* p) {
    uint32_t a;
    asm("{ .reg .u64 t; cvta.to.shared.u64 t, %1; cvt.u32.u64 %0, t; }"
        : "=r"(a) : "l"(p));
    return a;
}

__device__ __forceinline__ void ldsm_x4(uint32_t* r, uint32_t addr) {
    asm volatile("ldmatrix.sync.aligned.m8n8.x4.shared.b16 {%0,%1,%2,%3}, [%4];"
                 : "=r"(r[0]), "=r"(r[1]), "=r"(r[2]), "=r"(r[3]) : "r"(addr));
}

__device__ __forceinline__ void mma_f16(float* c, const uint32_t* a,
                                        uint32_t b0, uint32_t b1) {
    asm volatile(
        "mma.sync.aligned.m16n8k16.row.col.f32.f16.f16.f32 "
        "{%0,%1,%2,%3}, {%4,%5,%6,%7}, {%8,%9}, {%0,%1,%2,%3};"
        : "+f"(c[0]), "+f"(c[1]), "+f"(c[2]), "+f"(c[3])
        : "r"(a[0]), "r"(a[1]), "r"(a[2]), "r"(a[3]), "r"(b0), "r"(b1));
}

__device__ __forceinline__ void mbar_wait(uint32_t mbar, uint32_t parity) {
    asm volatile(
        "{\n\t"
        ".reg .pred P1;\n\t"
        "WAIT_LOOP_%=:\n\t"
        "mbarrier.try_wait.parity.acquire.cta.shared::cta.b64 P1, [%0], %1, 0x989680;\n\t"
        "@P1 bra.uni WAIT_DONE_%=;\n\t"
        "bra.uni WAIT_LOOP_%=;\n\t"
        "WAIT_DONE_%=:\n\t"
        "}"
        :: "r"(mbar), "r"(parity) : "memory");
}

__device__ __forceinline__ void mbar_arrive(uint32_t mbar) {
    asm volatile("mbarrier.arrive.release.cta.shared::cta.b64 _, [%0];"
                 :: "r"(mbar) : "memory");
}

// issue A half hh (CTA-local): tile hh>>4, support (hh>>1)&7, half hh&1.
__device__ __forceinline__ void issue_A(const float* __restrict__ X,
                                        uint32_t sb, int hh, int bid) {
    const int slot = hh % 3;
    const int tile = bid + (hh >> 4) * GRID;
    const int s    = (hh >> 1) & 7;
    const int row0 = tile * BLOCK_M + (hh & 1) * 64;
    int avail = NROWS - row0;
    uint32_t bytes;
    const float* src;
    if (avail >= 64)    { bytes = 64 * 512; src = X + ((size_t)s * NROWS + row0) * 128; }
    else if (avail > 0) { bytes = (uint32_t)avail * 512; src = X + ((size_t)s * NROWS + row0) * 128; }
    else                { bytes = 512; src = X; }
    const uint32_t mbar = sb + MB_AHF + slot * 8;
    asm volatile("mbarrier.arrive.expect_tx.shared.b64 _, [%0], %1;"
                 :: "r"(mbar), "r"(bytes) : "memory");
    asm volatile(
        "cp.async.bulk.shared::cta.global.mbarrier::complete_tx::bytes "
        "[%0], [%1], %2, [%3];"
        :: "r"(sb + SMEM_A0 + slot * AH_BYTES), "l"(src), "r"(bytes), "r"(mbar)
        : "memory");
}

// issue B for global support counter ss (content ss % 8) into slot ss&1
__device__ __forceinline__ void issue_B(uint32_t sb, int ss) {
    const int slot = ss & 1;
    const uint32_t mbar = sb + MB_BF + slot * 8;
    asm volatile("mbarrier.arrive.expect_tx.shared.b64 _, [%0], %1;"
                 :: "r"(mbar), "r"((uint32_t)B_BYTES) : "memory");
    const void* gB = (const void*)(g_Wh + (size_t)(ss & 7) * 16384);
    asm volatile(
        "cp.async.bulk.shared::cta.global.mbarrier::complete_tx::bytes "
        "[%0], [%1], %2, [%3];"
        :: "r"(sb + SMEM_B0 + slot * B_BYTES), "l"(gB), "r"((uint32_t)B_BYTES),
           "r"(mbar) : "memory");
}

// ---- prep: stage-major, ldmatrix-swizzled fp16 B ----------------------------

__global__ void prep_kernel(const float* __restrict__ W, const float* __restrict__ attn) {
    int idx = blockIdx.x * 256 + threadIdx.x;
    if (idx >= NSUP * 128 * 128) return;
    int s = idx >> 14;
    int o = (idx >> 7) & 127;
    int i = idx & 127;
    float v = attn[s] * W[((s << 7) + i) * 128 + o];
    int dst = s * 16384 + o * 128 + ((((i >> 3) ^ (o & 7))) << 3) + (i & 7);
    g_Wh[dst] = __float2half_rn(v);
}

// ---- main GEMM --------------------------------------------------------------

__global__ void __launch_bounds__(256, 1)
mgc_kernel(const float* __restrict__ X, const float* __restrict__ bias,
           float* __restrict__ out) {
    extern __shared__ char smem[];
    const uint32_t sb  = smem_u32(smem);
    const int tid = threadIdx.x;
    const int lid = tid & 31;
    const int bid = blockIdx.x;

    const int ntiles = (NTILES - bid + GRID - 1) / GRID;   // tiles for this CTA
    const int nsup_tot  = ntiles * NSUP;
    const int nhalf_tot = 2 * nsup_tot;

    if (tid == 0) {
        #pragma unroll
        for (int j = 0; j < 3; j++)
            asm volatile("mbarrier.init.shared.b64 [%0], 1;"
                         :: "r"(sb + MB_AHF + j * 8) : "memory");
        asm volatile("mbarrier.init.shared.b64 [%0], 1;" :: "r"(sb + MB_SF)     : "memory");
        asm volatile("mbarrier.init.shared.b64 [%0], 1;" :: "r"(sb + MB_SF + 8) : "memory");
        asm volatile("mbarrier.init.shared.b64 [%0], 1;" :: "r"(sb + MB_SE)     : "memory");
        asm volatile("mbarrier.init.shared.b64 [%0], 1;" :: "r"(sb + MB_SE + 8) : "memory");
        asm volatile("mbarrier.init.shared.b64 [%0], 1;" :: "r"(sb + MB_BF)     : "memory");
        asm volatile("mbarrier.init.shared.b64 [%0], 1;" :: "r"(sb + MB_BF + 8) : "memory");
        asm volatile("fence.proxy.async.shared::cta;" ::: "memory");
    }
    __syncthreads();
    if (tid == 128) {
        issue_A(X, sb, 0, bid);
        if (nhalf_tot > 1) issue_A(X, sb, 1, bid);
        if (nhalf_tot > 2) issue_A(X, sb, 2, bid);
        issue_B(sb, 0);
        if (nsup_tot > 1) issue_B(sb, 1);
    }

    if (tid >= 128) {
        // =================== PRODUCERS (warps 4-7) ==========================
        const int q = tid - 128;                 // 0..127
        for (int hh = 0; hh < nhalf_tot; hh++) {
            const int ss = hh >> 1;              // global support counter
            const int p  = ss & 1;               // staging slot
            if ((hh & 1) == 0 && ss >= 2)
                mbar_wait(sb + MB_SE + p * 8, ((ss - 2) >> 1) & 1);
            mbar_wait(sb + MB_AHF + (hh % 3) * 8, (uint32_t)((hh / 3) & 1));

            const uint32_t aSlot = sb + SMEM_A0 + (hh % 3) * AH_BYTES;
            const uint32_t stg   = sb + SMEM_STG + p * STG_BYTES;
            const int rowoff = (hh & 1) * 64;
            #pragma unroll
            for (int i = 0; i < 16; i++) {
                int f  = q + (i << 7);           // 0..2047
                int c  = f >> 9;
                int rw = (f >> 3) & 63;
                int fc = f & 7;
                float x, y, z, w;
                asm("ld.shared.v4.f32 {%0,%1,%2,%3}, [%4];"
                    : "=f"(x), "=f"(y), "=f"(z), "=f"(w)
                    : "r"(aSlot + (uint32_t)(rw * 512 + c * 128 + fc * 16)));
                uint32_t h0, h1;
                asm("cvt.rn.f16x2.f32 %0, %1, %2;" : "=r"(h0) : "f"(y), "f"(x));
                asm("cvt.rn.f16x2.f32 %0, %1, %2;" : "=r"(h1) : "f"(w), "f"(z));
                int grow = rw + rowoff;
                int phys = (fc >> 1) ^ ((rw >> 1) & 3);
                asm volatile("st.shared.v2.b32 [%0], {%1,%2};"
                    :: "r"(stg + (uint32_t)(c * 8192 + grow * 64 + phys * 16 + (fc & 1) * 8)),
                       "r"(h0), "r"(h1) : "memory");
            }
            asm volatile("bar.sync 1, 128;" ::: "memory");   // producers only
            if (tid == 128) {
                if (hh + 3 < nhalf_tot) issue_A(X, sb, hh + 3, bid);
                if (hh & 1) mbar_arrive(sb + MB_SF + p * 8);
            }
        }
    } else {
        // =================== CONSUMERS (warps 0-3, 64x64 tiles) ============
        const int wid = tid >> 5;
        const int wm  = wid >> 1;
        const int wn  = wid & 1;

        const int rA_base = wm * 64 + (lid & 15);
        const int a_usel  = (lid >> 4) & 1;
        const int o_base  = wn * 64 + (lid & 7) + ((lid >> 4) & 1) * 8;
        const int b_usel  = (lid >> 3) & 1;
        const int tig = lid & 3;
        const int g   = lid >> 2;

        float2 bv[8];
        #pragma unroll
        for (int nt = 0; nt < 8; nt++) {
            int cidx = wn * 64 + nt * 8 + 2 * tig;
            bv[nt].x = __ldg(&bias[cidx]);
            bv[nt].y = __ldg(&bias[cidx + 1]);
        }

        for (int tile = 0; tile < ntiles; tile++) {
            const int m0 = (bid + tile * GRID) * BLOCK_M;

            float acc[4][8][4];
            #pragma unroll
            for (int mt = 0; mt < 4; mt++)
                #pragma unroll
                for (int nt = 0; nt < 8; nt++)
                    #pragma unroll
                    for (int v = 0; v < 4; v++) acc[mt][nt][v] = 0.f;

            for (int s = 0; s < NSUP; s++) {
                const int ss = tile * NSUP + s;
                const int p  = ss & 1;
                const uint32_t par = (ss >> 1) & 1;
                mbar_wait(sb + MB_SF + p * 8, par);
                mbar_wait(sb + MB_BF + p * 8, par);

                const uint32_t stg   = sb + SMEM_STG + p * STG_BYTES;
                const uint32_t bSlot = sb + SMEM_B0 + p * B_BYTES;

                #pragma unroll
                for (int c = 0; c < 4; c++) {
                    #pragma unroll
                    for (int jl = 0; jl < 2; jl++) {
                        uint32_t af[4][4];
                        #pragma unroll
                        for (int mt = 0; mt < 4; mt++) {
                            int r = rA_base + mt * 16;
                            int u = 2 * jl + a_usel;
                            uint32_t addr = stg + (uint32_t)(c * 8192 + r * 64 +
                                               ((u ^ ((r >> 1) & 3)) << 4));
                            ldsm_x4(af[mt], addr);
                        }
                        uint32_t bq[4][4];
                        #pragma unroll
                        for (int pp = 0; pp < 4; pp++) {
                            int o = o_base + 16 * pp;
                            int u = 4 * c + 2 * jl + b_usel;
                            uint32_t addr = bSlot + (uint32_t)(o * 256 +
                                                ((u ^ (o & 7)) << 4));
                            ldsm_x4(bq[pp], addr);
                        }
                        #pragma unroll
                        for (int mt = 0; mt < 4; mt++)
                            #pragma unroll
                            for (int pp = 0; pp < 4; pp++) {
                                mma_f16(acc[mt][2 * pp],     af[mt], bq[pp][0], bq[pp][1]);
                                mma_f16(acc[mt][2 * pp + 1], af[mt], bq[pp][2], bq[pp][3]);
                            }
                    }
                }

                asm volatile("bar.sync 2, 128;" ::: "memory");
                if (tid == 0) {
                    mbar_arrive(sb + MB_SE + p * 8);
                    if (ss + 2 < nsup_tot) issue_B(sb, ss + 2);
                }
            }

            // ---- epilogue for this tile (producers keep streaming) ----------
            #pragma unroll
            for (int mt = 0; mt < 4; mt++) {
                int mrow = m0 + wm * 64 + mt * 16 + g;
                #pragma unroll
                for (int half = 0; half < 2; half++) {
                    int m = mrow + half * 8;
                    if (m < NROWS) {
                        float* po = out + (size_t)m * 128 + wn * 64;
                        #pragma unroll
                        for (int nt = 0; nt < 8; nt++) {
                            float2 v;
                            v.x = acc[mt][nt][2 * half + 0] + bv[nt].x;
                            v.y = acc[mt][nt][2 * half + 1] + bv[nt].y;
                            *reinterpret_cast<float2*>(po + nt * 8 + 2 * tig) = v;
                        }
                    }
                }
            }
        }
    }
}

// ---- launch -----------------------------------------------------------------

extern "C" void kernel_launch(void* const* d_in, const int* in_sizes, int n_in,
                              void* d_out, int out_size) {
    const float* X    = (const float*)d_in[0];   // (8, 200000, 128) f32
    const float* W    = (const float*)d_in[1];   // (8, 128, 128)    f32
    const float* attn = (const float*)d_in[2];   // (8,)             f32
    const float* bias = (const float*)d_in[3];   // (128,)           f32
    float* out = (float*)d_out;                  // (200000, 128)    f32

    cudaFuncSetAttribute(mgc_kernel, cudaFuncAttributeMaxDynamicSharedMemorySize,
                         SMEM_TOTAL);

    prep_kernel<<<(NSUP * 128 * 128 + 255) / 256, 256>>>(W, attn);

    mgc_kernel<<<GRID, 256, SMEM_TOTAL>>>(X, bias, out);
}

// round 12
// speedup vs baseline: 1.3477x; 1.0127x over previous
#include <cuda_runtime.h>
#include <cuda_fp16.h>
#include <cstdint>

// ---------------------------------------------------------------------------
// out[n,o] = sum_s attn[s] * (X[s] @ W[s])[n,o] + bias[o]
// R12: persistent CTAs; per-HALF producer->consumer handoff. Warp pair wm
//      consumes only staging half wm -> two decoupled dependency chains.
// ---------------------------------------------------------------------------

#define NROWS    200000
#define BLOCK_M  128
#define NSUP     8
#define NTILES   1563
#define GRID     148

#define AH_BYTES  32768             // 64 rows x 512B fp32 (half support)
#define STG_BYTES 32768             // 128 x 128 fp16 (swizzled)
#define B_BYTES   32768

// mbarriers (byte offsets in smem)
#define MB_AHF 0                    // 3 slots x 8B (tx)
#define MB_SF  24                   // [p][h] 4 x 8B (count 1)
#define MB_SE  56                   // [p][h] 4 x 8B (count 2)
#define MB_BF  88                   // 2 x 8B (tx)
#define MB_BE  104                  // 2 x 8B (count 4)

#define SMEM_A0   1024
#define SMEM_STG  (SMEM_A0 + 3 * AH_BYTES)
#define SMEM_B0   (SMEM_STG + 2 * STG_BYTES)
#define SMEM_TOTAL (SMEM_B0 + 2 * B_BYTES)       // 231424

// B: stage-major fp16, attn-folded, swizzled: (s,o,i) ->
//   s*16384 + o*128 + ((i>>3) ^ (o&7))*8 + (i&7)
__device__ __half g_Wh[NSUP * 128 * 128];

// ---- helpers ---------------------------------------------------------------

__device__ __forceinline__ uint32_t smem_u32(const void* p) {
    uint32_t a;
    asm("{ .reg .u64 t; cvta.to.shared.u64 t, %1; cvt.u32.u64 %0, t; }"
        : "=r"(a) : "l"(p));
    return a;
}

__device__ __forceinline__ void ldsm_x4(uint32_t* r, uint32_t addr) {
    asm volatile("ldmatrix.sync.aligned.m8n8.x4.shared.b16 {%0,%1,%2,%3}, [%4];"
                 : "=r"(r[0]), "=r"(r[1]), "=r"(r[2]), "=r"(r[3]) : "r"(addr));
}

__device__ __forceinline__ void mma_f16(float* c, const uint32_t* a,
                                        uint32_t b0, uint32_t b1) {
    asm volatile(
        "mma.sync.aligned.m16n8k16.row.col.f32.f16.f16.f32 "
        "{%0,%1,%2,%3}, {%4,%5,%6,%7}, {%8,%9}, {%0,%1,%2,%3};"
        : "+f"(c[0]), "+f"(c[1]), "+f"(c[2]), "+f"(c[3])
        : "r"(a[0]), "r"(a[1]), "r"(a[2]), "r"(a[3]), "r"(b0), "r"(b1));
}

__device__ __forceinline__ void mbar_wait(uint32_t mbar, uint32_t parity) {
    asm volatile(
        "{\n\t"
        ".reg .pred P1;\n\t"
        "WAIT_LOOP_%=:\n\t"
        "mbarrier.try_wait.parity.acquire.cta.shared::cta.b64 P1, [%0], %1, 0x989680;\n\t"
        "@P1 bra.uni WAIT_DONE_%=;\n\t"
        "bra.uni WAIT_LOOP_%=;\n\t"
        "WAIT_DONE_%=:\n\t"
        "}"
        :: "r"(mbar), "r"(parity) : "memory");
}

__device__ __forceinline__ void mbar_arrive(uint32_t mbar) {
    asm volatile("mbarrier.arrive.release.cta.shared::cta.b64 _, [%0];"
                 :: "r"(mbar) : "memory");
}

// issue A half hh (CTA-local): tile hh>>4, support (hh>>1)&7, half hh&1.
__device__ __forceinline__ void issue_A(const float* __restrict__ X,
                                        uint32_t sb, int hh, int bid) {
    const int slot = hh % 3;
    const int tile = bid + (hh >> 4) * GRID;
    const int s    = (hh >> 1) & 7;
    const int row0 = tile * BLOCK_M + (hh & 1) * 64;
    int avail = NROWS - row0;
    uint32_t bytes;
    const float* src;
    if (avail >= 64)    { bytes = 64 * 512; src = X + ((size_t)s * NROWS + row0) * 128; }
    else if (avail > 0) { bytes = (uint32_t)avail * 512; src = X + ((size_t)s * NROWS + row0) * 128; }
    else                { bytes = 512; src = X; }
    const uint32_t mbar = sb + MB_AHF + slot * 8;
    asm volatile("mbarrier.arrive.expect_tx.shared.b64 _, [%0], %1;"
                 :: "r"(mbar), "r"(bytes) : "memory");
    asm volatile(
        "cp.async.bulk.shared::cta.global.mbarrier::complete_tx::bytes "
        "[%0], [%1], %2, [%3];"
        :: "r"(sb + SMEM_A0 + slot * AH_BYTES), "l"(src), "r"(bytes), "r"(mbar)
        : "memory");
}

// issue B for global support counter ss (content ss % 8) into slot ss&1
__device__ __forceinline__ void issue_B(uint32_t sb, int ss) {
    const int slot = ss & 1;
    const uint32_t mbar = sb + MB_BF + slot * 8;
    asm volatile("mbarrier.arrive.expect_tx.shared.b64 _, [%0], %1;"
                 :: "r"(mbar), "r"((uint32_t)B_BYTES) : "memory");
    const void* gB = (const void*)(g_Wh + (size_t)(ss & 7) * 16384);
    asm volatile(
        "cp.async.bulk.shared::cta.global.mbarrier::complete_tx::bytes "
        "[%0], [%1], %2, [%3];"
        :: "r"(sb + SMEM_B0 + slot * B_BYTES), "l"(gB), "r"((uint32_t)B_BYTES),
           "r"(mbar) : "memory");
}

// ---- prep: stage-major, ldmatrix-swizzled fp16 B ----------------------------

__global__ void prep_kernel(const float* __restrict__ W, const float* __restrict__ attn) {
    int idx = blockIdx.x * 256 + threadIdx.x;
    if (idx >= NSUP * 128 * 128) return;
    int s = idx >> 14;
    int o = (idx >> 7) & 127;
    int i = idx & 127;
    float v = attn[s] * W[((s << 7) + i) * 128 + o];
    int dst = s * 16384 + o * 128 + ((((i >> 3) ^ (o & 7))) << 3) + (i & 7);
    g_Wh[dst] = __float2half_rn(v);
}

// ---- main GEMM --------------------------------------------------------------

__global__ void __launch_bounds__(256, 1)
mgc_kernel(const float* __restrict__ X, const float* __restrict__ bias,
           float* __restrict__ out) {
    extern __shared__ char smem[];
    const uint32_t sb  = smem_u32(smem);
    const int tid = threadIdx.x;
    const int lid = tid & 31;
    const int bid = blockIdx.x;

    const int ntiles = (NTILES - bid + GRID - 1) / GRID;
    const int nsup_tot  = ntiles * NSUP;
    const int nhalf_tot = 2 * nsup_tot;

    if (tid == 0) {
        #pragma unroll
        for (int j = 0; j < 3; j++)
            asm volatile("mbarrier.init.shared.b64 [%0], 1;"
                         :: "r"(sb + MB_AHF + j * 8) : "memory");
        #pragma unroll
        for (int j = 0; j < 4; j++) {
            asm volatile("mbarrier.init.shared.b64 [%0], 1;"
                         :: "r"(sb + MB_SF + j * 8) : "memory");
            asm volatile("mbarrier.init.shared.b64 [%0], 2;"
                         :: "r"(sb + MB_SE + j * 8) : "memory");
        }
        asm volatile("mbarrier.init.shared.b64 [%0], 1;" :: "r"(sb + MB_BF)     : "memory");
        asm volatile("mbarrier.init.shared.b64 [%0], 1;" :: "r"(sb + MB_BF + 8) : "memory");
        asm volatile("mbarrier.init.shared.b64 [%0], 4;" :: "r"(sb + MB_BE)     : "memory");
        asm volatile("mbarrier.init.shared.b64 [%0], 4;" :: "r"(sb + MB_BE + 8) : "memory");
        asm volatile("fence.proxy.async.shared::cta;" ::: "memory");
    }
    __syncthreads();
    if (tid == 128) {
        issue_A(X, sb, 0, bid);
        if (nhalf_tot > 1) issue_A(X, sb, 1, bid);
        if (nhalf_tot > 2) issue_A(X, sb, 2, bid);
        issue_B(sb, 0);
        if (nsup_tot > 1) issue_B(sb, 1);
    }

    if (tid >= 128) {
        // =================== PRODUCERS (warps 4-7) ==========================
        const int q = tid - 128;                 // 0..127
        for (int hh = 0; hh < nhalf_tot; hh++) {
            const int ss = hh >> 1;
            const int h  = hh & 1;
            const int p  = ss & 1;
            if (ss >= 2)                          // half h of stg[p] free?
                mbar_wait(sb + MB_SE + (p * 16 + h * 8), ((ss - 2) >> 1) & 1);
            mbar_wait(sb + MB_AHF + (hh % 3) * 8, (uint32_t)((hh / 3) & 1));

            const uint32_t aSlot = sb + SMEM_A0 + (hh % 3) * AH_BYTES;
            const uint32_t stg   = sb + SMEM_STG + p * STG_BYTES;
            const int rowoff = h * 64;
            #pragma unroll
            for (int i = 0; i < 16; i++) {
                int f  = q + (i << 7);           // 0..2047
                int c  = f >> 9;
                int rw = (f >> 3) & 63;
                int fc = f & 7;
                float x, y, z, w;
                asm("ld.shared.v4.f32 {%0,%1,%2,%3}, [%4];"
                    : "=f"(x), "=f"(y), "=f"(z), "=f"(w)
                    : "r"(aSlot + (uint32_t)(rw * 512 + c * 128 + fc * 16)));
                uint32_t h0, h1;
                asm("cvt.rn.f16x2.f32 %0, %1, %2;" : "=r"(h0) : "f"(y), "f"(x));
                asm("cvt.rn.f16x2.f32 %0, %1, %2;" : "=r"(h1) : "f"(w), "f"(z));
                int grow = rw + rowoff;
                int phys = (fc >> 1) ^ ((rw >> 1) & 3);
                asm volatile("st.shared.v2.b32 [%0], {%1,%2};"
                    :: "r"(stg + (uint32_t)(c * 8192 + grow * 64 + phys * 16 + (fc & 1) * 8)),
                       "r"(h0), "r"(h1) : "memory");
            }
            asm volatile("bar.sync 1, 128;" ::: "memory");   // producers only
            if (tid == 128) {
                if (hh + 3 < nhalf_tot) issue_A(X, sb, hh + 3, bid);
                mbar_arrive(sb + MB_SF + (p * 16 + h * 8));  // half ready
            }
        }
    } else {
        // =================== CONSUMERS (warps 0-3, 64x64 tiles) ============
        const int wid = tid >> 5;
        const int wm  = wid >> 1;                // pair id == staging half
        const int wn  = wid & 1;

        const int rA_base = wm * 64 + (lid & 15);
        const int a_usel  = (lid >> 4) & 1;
        const int o_base  = wn * 64 + (lid & 7) + ((lid >> 4) & 1) * 8;
        const int b_usel  = (lid >> 3) & 1;
        const int tig = lid & 3;
        const int g   = lid >> 2;

        float2 bv[8];
        #pragma unroll
        for (int nt = 0; nt < 8; nt++) {
            int cidx = wn * 64 + nt * 8 + 2 * tig;
            bv[nt].x = __ldg(&bias[cidx]);
            bv[nt].y = __ldg(&bias[cidx + 1]);
        }

        for (int tile = 0; tile < ntiles; tile++) {
            const int m0 = (bid + tile * GRID) * BLOCK_M;

            float acc[4][8][4];
            #pragma unroll
            for (int mt = 0; mt < 4; mt++)
                #pragma unroll
                for (int nt = 0; nt < 8; nt++)
                    #pragma unroll
                    for (int v = 0; v < 4; v++) acc[mt][nt][v] = 0.f;

            for (int s = 0; s < NSUP; s++) {
                const int ss = tile * NSUP + s;
                const int p  = ss & 1;
                const uint32_t par = (ss >> 1) & 1;
                mbar_wait(sb + MB_SF + (p * 16 + wm * 8), par);  // my half only
                mbar_wait(sb + MB_BF + p * 8, par);

                const uint32_t stg   = sb + SMEM_STG + p * STG_BYTES;
                const uint32_t bSlot = sb + SMEM_B0 + p * B_BYTES;

                #pragma unroll
                for (int c = 0; c < 4; c++) {
                    #pragma unroll
                    for (int jl = 0; jl < 2; jl++) {
                        uint32_t af[4][4];
                        #pragma unroll
                        for (int mt = 0; mt < 4; mt++) {
                            int r = rA_base + mt * 16;
                            int u = 2 * jl + a_usel;
                            uint32_t addr = stg + (uint32_t)(c * 8192 + r * 64 +
                                               ((u ^ ((r >> 1) & 3)) << 4));
                            ldsm_x4(af[mt], addr);
                        }
                        uint32_t bq[4][4];
                        #pragma unroll
                        for (int pp = 0; pp < 4; pp++) {
                            int o = o_base + 16 * pp;
                            int u = 4 * c + 2 * jl + b_usel;
                            uint32_t addr = bSlot + (uint32_t)(o * 256 +
                                                ((u ^ (o & 7)) << 4));
                            ldsm_x4(bq[pp], addr);
                        }
                        #pragma unroll
                        for (int mt = 0; mt < 4; mt++)
                            #pragma unroll
                            for (int pp = 0; pp < 4; pp++) {
                                mma_f16(acc[mt][2 * pp],     af[mt], bq[pp][0], bq[pp][1]);
                                mma_f16(acc[mt][2 * pp + 1], af[mt], bq[pp][2], bq[pp][3]);
                            }
                    }
                }

                __syncwarp();
                if (lid == 0) {
                    mbar_arrive(sb + MB_SE + (p * 16 + wm * 8));  // my half free
                    mbar_arrive(sb + MB_BE + p * 8);              // done with B
                }
                if (tid == 0 && ss + 2 < nsup_tot) {
                    mbar_wait(sb + MB_BE + p * 8, par);           // all 4 done
                    issue_B(sb, ss + 2);
                }
            }

            // ---- epilogue for this tile (producers keep streaming) ----------
            #pragma unroll
            for (int mt = 0; mt < 4; mt++) {
                int mrow = m0 + wm * 64 + mt * 16 + g;
                #pragma unroll
                for (int half = 0; half < 2; half++) {
                    int m = mrow + half * 8;
                    if (m < NROWS) {
                        float* po = out + (size_t)m * 128 + wn * 64;
                        #pragma unroll
                        for (int nt = 0; nt < 8; nt++) {
                            float2 v;
                            v.x = acc[mt][nt][2 * half + 0] + bv[nt].x;
                            v.y = acc[mt][nt][2 * half + 1] + bv[nt].y;
                            *reinterpret_cast<float2*>(po + nt * 8 + 2 * tig) = v;
                        }
                    }
                }
            }
        }
    }
}

// ---- launch -----------------------------------------------------------------

extern "C" void kernel_launch(void* const* d_in, const int* in_sizes, int n_in,
                              void* d_out, int out_size) {
    const float* X    = (const float*)d_in[0];   // (8, 200000, 128) f32
    const float* W    = (const float*)d_in[1];   // (8, 128, 128)    f32
    const float* attn = (const float*)d_in[2];   // (8,)             f32
    const float* bias = (const float*)d_in[3];   // (128,)           f32
    float* out = (float*)d_out;                  // (200000, 128)    f32

    cudaFuncSetAttribute(mgc_kernel, cudaFuncAttributeMaxDynamicSharedMemorySize,
                         SMEM_TOTAL);

    prep_kernel<<<(NSUP * 128 * 128 + 255) / 256, 256>>>(W, attn);

    mgc_kernel<<<GRID, 256, SMEM_TOTAL>>>(X, bias, out);
}